// round 4
// baseline (speedup 1.0000x reference)
#include <cuda_runtime.h>
#include <cuda_bf16.h>
#include <math.h>

// Problem constants
#define B_DIM 8192
#define D_DIM 1024
#define K_DIM 2048
#define E_DIM 512
#define BETA_F 0.001f

// ---------------------------------------------------------------------------
// Scratch (device globals: allocation-free per harness rules)
// ---------------------------------------------------------------------------
__device__ float g_S[(size_t)B_DIM * K_DIM];     // cross buffer (reused for G1 & G3 outputs)
__device__ float g_XP[(size_t)B_DIM * K_DIM];    // softmax outputs xp / yp (reused)
__device__ float g_LAT[(size_t)B_DIM * E_DIM];   // lat
__device__ float g_REC[(size_t)B_DIM * D_DIM];   // recon
__device__ float g_C2[K_DIM];                    // mean_d project_w[k,:]^2
__device__ float g_C2B[K_DIM];                   // mean_e rec_w[:,k]^2

// ---------------------------------------------------------------------------
// SGEMM: C[M,N] = A[M,Kd] * op(B)
//   TRANSB=true : B is (N, Kd) row-major  -> C = A * B^T   (NT)
//   TRANSB=false: B is (Kd, N) row-major  -> C = A * B     (NN)
// Tiles: 128x128x16, 256 threads, 8x8 microtile (split 4+4 across 64-halves),
// double-buffered shared memory. All dims assumed multiples of tile sizes.
// ---------------------------------------------------------------------------
#define BM 128
#define BN 128
#define BKK 16

__device__ __forceinline__ void g_load_rowmajor16(const float* __restrict__ P, int ld,
                                                  int row0, int col0, int t,
                                                  float4& v0, float4& v1) {
    // 128 rows x 16 cols tile from row-major matrix, 2 float4 per thread
    int r = t >> 2;        // 0..63  (second load at r+64)
    int c = t & 3;         // 0..3   (float4 index within 16 cols)
    const float* p = P + (size_t)(row0 + r) * ld + col0 + c * 4;
    v0 = *(const float4*)p;
    v1 = *(const float4*)(p + (size_t)64 * ld);
}

__device__ __forceinline__ void s_store_transposed(float (*Sb)[BM + 4], int t,
                                                   float4 v0, float4 v1) {
    int r = t >> 2;
    int c = t & 3;
    Sb[c * 4 + 0][r] = v0.x; Sb[c * 4 + 1][r] = v0.y;
    Sb[c * 4 + 2][r] = v0.z; Sb[c * 4 + 3][r] = v0.w;
    Sb[c * 4 + 0][r + 64] = v1.x; Sb[c * 4 + 1][r + 64] = v1.y;
    Sb[c * 4 + 2][r + 64] = v1.z; Sb[c * 4 + 3][r + 64] = v1.w;
}

__device__ __forceinline__ void g_load_kmajor16(const float* __restrict__ P, int ld,
                                                int krow0, int col0, int t,
                                                float4& v0, float4& v1) {
    // 16 rows x 128 cols tile from row-major (Kd x N) matrix
    int kk = t >> 5;       // 0..7 (second load at kk+8)
    int c = t & 31;        // 0..31 float4 index
    const float* p = P + (size_t)(krow0 + kk) * ld + col0 + c * 4;
    v0 = *(const float4*)p;
    v1 = *(const float4*)(p + (size_t)8 * ld);
}

__device__ __forceinline__ void s_store_direct(float (*Sb)[BN + 4], int t,
                                               float4 v0, float4 v1) {
    int kk = t >> 5;
    int c = t & 31;
    *(float4*)&Sb[kk][c * 4] = v0;
    *(float4*)&Sb[kk + 8][c * 4] = v1;
}

template <bool TRANSB>
__global__ __launch_bounds__(256, 2)
void gemm_kernel(float* __restrict__ C, const float* __restrict__ A,
                 const float* __restrict__ B, int M, int N, int Kd) {
    __shared__ __align__(16) float As[2][BKK][BM + 4];
    __shared__ __align__(16) float Bs[2][BKK][BN + 4];

    const int t  = threadIdx.x;
    const int m0 = blockIdx.y * BM;
    const int n0 = blockIdx.x * BN;
    const int tx = t & 15;
    const int ty = t >> 4;
    const int nk = Kd / BKK;

    float acc[8][8];
#pragma unroll
    for (int i = 0; i < 8; i++)
#pragma unroll
        for (int j = 0; j < 8; j++) acc[i][j] = 0.0f;

    // Prologue: tile 0
    {
        float4 a0, a1, b0, b1;
        g_load_rowmajor16(A, Kd, m0, 0, t, a0, a1);
        s_store_transposed(As[0], t, a0, a1);
        if (TRANSB) {
            g_load_rowmajor16(B, Kd, n0, 0, t, b0, b1);
            s_store_transposed(Bs[0], t, b0, b1);
        } else {
            g_load_kmajor16(B, N, 0, n0, t, b0, b1);
            s_store_direct(Bs[0], t, b0, b1);
        }
    }
    __syncthreads();

    for (int kt = 0; kt < nk; ++kt) {
        const int buf = kt & 1;
        float4 a0, a1, b0, b1;
        const bool has_next = (kt + 1 < nk);
        if (has_next) {
            g_load_rowmajor16(A, Kd, m0, (kt + 1) * BKK, t, a0, a1);
            if (TRANSB) {
                g_load_rowmajor16(B, Kd, n0, (kt + 1) * BKK, t, b0, b1);
            } else {
                g_load_kmajor16(B, N, (kt + 1) * BKK, n0, t, b0, b1);
            }
        }

#pragma unroll
        for (int k = 0; k < BKK; k++) {
            float a[8], b[8];
            *(float4*)&a[0] = *(const float4*)&As[buf][k][ty * 4];
            *(float4*)&a[4] = *(const float4*)&As[buf][k][64 + ty * 4];
            *(float4*)&b[0] = *(const float4*)&Bs[buf][k][tx * 4];
            *(float4*)&b[4] = *(const float4*)&Bs[buf][k][64 + tx * 4];
#pragma unroll
            for (int i = 0; i < 8; i++)
#pragma unroll
                for (int j = 0; j < 8; j++) acc[i][j] += a[i] * b[j];
        }

        if (has_next) {
            const int nb = buf ^ 1;
            s_store_transposed(As[nb], t, a0, a1);
            if (TRANSB) s_store_transposed(Bs[nb], t, b0, b1);
            else        s_store_direct(Bs[nb], t, b0, b1);
        }
        __syncthreads();
    }

    // Epilogue: rows {ty*4+i, 64+ty*4+i}, cols {tx*4+j, 64+tx*4+j}
#pragma unroll
    for (int i = 0; i < 8; i++) {
        int row = m0 + ((i < 4) ? (ty * 4 + i) : (64 + ty * 4 + (i - 4)));
        float4 lo = make_float4(acc[i][0], acc[i][1], acc[i][2], acc[i][3]);
        float4 hi = make_float4(acc[i][4], acc[i][5], acc[i][6], acc[i][7]);
        *(float4*)(C + (size_t)row * N + n0 + tx * 4) = lo;
        *(float4*)(C + (size_t)row * N + n0 + 64 + tx * 4) = hi;
    }
}

// ---------------------------------------------------------------------------
// Helpers: block reductions (deterministic tree reduction)
// ---------------------------------------------------------------------------
__device__ __forceinline__ float block_reduce_max(float v, float* red) {
    int t = threadIdx.x;
    red[t] = v;
    __syncthreads();
#pragma unroll
    for (int s = 128; s > 0; s >>= 1) {
        if (t < s) red[t] = fmaxf(red[t], red[t + s]);
        __syncthreads();
    }
    float r = red[0];
    __syncthreads();
    return r;
}

__device__ __forceinline__ float block_reduce_sum(float v, float* red) {
    int t = threadIdx.x;
    red[t] = v;
    __syncthreads();
#pragma unroll
    for (int s = 128; s > 0; s >>= 1) {
        if (t < s) red[t] = red[t] + red[t + s];
        __syncthreads();
    }
    float r = red[0];
    __syncthreads();
    return r;
}

// ---------------------------------------------------------------------------
// Row softmax over K=2048 columns.
// logit[k] = a * S[row,k] - BETA * c2[k]   (per-row x2 term dropped: constant
// along the softmax axis => shift-invariant, identical result)
// ---------------------------------------------------------------------------
__global__ void softmax_kernel(const float* __restrict__ S, float* __restrict__ O,
                               const float* __restrict__ c2, float a) {
    __shared__ float red[256];
    const int row = blockIdx.x;
    const int t = threadIdx.x;
    const float* s = S + (size_t)row * K_DIM;
    float* o = O + (size_t)row * K_DIM;

    float vals[8];
    float mx = -INFINITY;
#pragma unroll
    for (int i = 0; i < 8; i++) {
        int k = t + i * 256;
        float v = a * s[k] - BETA_F * c2[k];
        vals[i] = v;
        mx = fmaxf(mx, v);
    }
    mx = block_reduce_max(mx, red);

    float sum = 0.0f;
#pragma unroll
    for (int i = 0; i < 8; i++) {
        vals[i] = expf(vals[i] - mx);
        sum += vals[i];
    }
    sum = block_reduce_sum(sum, red);
    float inv = 1.0f / sum;
#pragma unroll
    for (int i = 0; i < 8; i++) o[t + i * 256] = vals[i] * inv;
}

// mean of squares along each row: out[r] = mean_c W[r,c]^2   (project_w: K x D)
__global__ void rowmeansq_kernel(const float* __restrict__ W, float* __restrict__ out,
                                 int cols) {
    __shared__ float red[256];
    const int row = blockIdx.x;
    const int t = threadIdx.x;
    const float* w = W + (size_t)row * cols;
    float s = 0.0f;
    for (int c = t; c < cols; c += 256) {
        float v = w[c];
        s += v * v;
    }
    s = block_reduce_sum(s, red);
    if (t == 0) out[row] = s / (float)cols;
}

// mean of squares along each column: out[k] = mean_e W[e,k]^2   (rec_w: E x K)
__global__ void colmeansq_kernel(const float* __restrict__ W, float* __restrict__ out,
                                 int rows, int cols) {
    int k = blockIdx.x * blockDim.x + threadIdx.x;
    if (k < cols) {
        float s = 0.0f;
        for (int e = 0; e < rows; e++) {
            float v = W[(size_t)e * cols + k];
            s += v * v;
        }
        out[k] = s / (float)rows;
    }
}

// loss[b] = mean_d (recon[b,d] - img[b,d])^2
__global__ void loss_kernel(const float* __restrict__ recon, const float* __restrict__ img,
                            float* __restrict__ out, int cols) {
    __shared__ float red[256];
    const int row = blockIdx.x;
    const int t = threadIdx.x;
    const float* r = recon + (size_t)row * cols;
    const float* x = img + (size_t)row * cols;
    float s = 0.0f;
    for (int c = t; c < cols; c += 256) {
        float d = r[c] - x[c];
        s += d * d;
    }
    s = block_reduce_sum(s, red);
    if (t == 0) out[row] = s / (float)cols;
}

// ---------------------------------------------------------------------------
// Launch
// ---------------------------------------------------------------------------
extern "C" void kernel_launch(void* const* d_in, const int* in_sizes, int n_in,
                              void* d_out, int out_size) {
    const float* images    = (const float*)d_in[0];   // (B, D)
    const float* project_w = (const float*)d_in[1];   // (K, D)
    const float* rec_w     = (const float*)d_in[2];   // (E, K)
    float* loss_out        = (float*)d_out;           // (B,)

    float *S, *XP, *LAT, *REC, *C2, *C2B;
    cudaGetSymbolAddress((void**)&S,   g_S);
    cudaGetSymbolAddress((void**)&XP,  g_XP);
    cudaGetSymbolAddress((void**)&LAT, g_LAT);
    cudaGetSymbolAddress((void**)&REC, g_REC);
    cudaGetSymbolAddress((void**)&C2,  g_C2);
    cudaGetSymbolAddress((void**)&C2B, g_C2B);

    // Column-norm precomputes
    rowmeansq_kernel<<<K_DIM, 256>>>(project_w, C2, D_DIM);
    colmeansq_kernel<<<K_DIM / 256, 256>>>(rec_w, C2B, E_DIM, K_DIM);

    // G1 (NT): S = images @ project_w^T   (B x K)
    gemm_kernel<true><<<dim3(K_DIM / BN, B_DIM / BM), 256>>>(
        S, images, project_w, B_DIM, K_DIM, D_DIM);

    // softmax1: xp = softmax(BETA*(2/D * S - c2))
    softmax_kernel<<<B_DIM, 256>>>(S, XP, C2, BETA_F * 2.0f / (float)D_DIM);

    // G2 (NT): lat = xp @ rec_w^T   (B x E)
    gemm_kernel<true><<<dim3(E_DIM / BN, B_DIM / BM), 256>>>(
        LAT, XP, rec_w, B_DIM, E_DIM, K_DIM);

    // G3 (NN): S = lat @ rec_w   (B x K)
    gemm_kernel<false><<<dim3(K_DIM / BN, B_DIM / BM), 256>>>(
        S, LAT, rec_w, B_DIM, K_DIM, E_DIM);

    // softmax2: yp = softmax(BETA*(2/E * S - c2b))
    softmax_kernel<<<B_DIM, 256>>>(S, XP, C2B, BETA_F * 2.0f / (float)E_DIM);

    // G4 (NN): recon = yp @ project_w   (B x D)
    gemm_kernel<false><<<dim3(D_DIM / BN, B_DIM / BM), 256>>>(
        REC, XP, project_w, B_DIM, D_DIM, K_DIM);

    // loss[b] = mean_d (recon - images)^2
    loss_kernel<<<B_DIM, 256>>>(REC, images, loss_out, D_DIM);
}

// round 5
// speedup vs baseline: 8.6319x; 8.6319x over previous
#include <cuda_runtime.h>
#include <cuda_bf16.h>
#include <math.h>
#include <stdint.h>

// Problem constants
#define B_DIM 8192
#define D_DIM 1024
#define K_DIM 2048
#define E_DIM 512
#define BETA_F 0.001f

// ---------------------------------------------------------------------------
// Scratch (device globals: allocation-free per harness rules)
// ---------------------------------------------------------------------------
__device__ __align__(256) float g_S[(size_t)B_DIM * K_DIM];      // fp32 cross buffer (G1 & G3 out)
__device__ __align__(256) float g_REC[(size_t)B_DIM * D_DIM];    // recon fp32
__device__ __align__(256) float g_C2[K_DIM];
__device__ __align__(256) float g_C2B[K_DIM];

__device__ __align__(256) __nv_bfloat16 g_IMG_BF[(size_t)B_DIM * D_DIM];   // images bf16
__device__ __align__(256) __nv_bfloat16 g_PW_BF[(size_t)K_DIM * D_DIM];    // project_w (K,D)
__device__ __align__(256) __nv_bfloat16 g_PWT_BF[(size_t)D_DIM * K_DIM];   // project_w^T (D,K)
__device__ __align__(256) __nv_bfloat16 g_RW_BF[(size_t)E_DIM * K_DIM];    // rec_w (E,K)
__device__ __align__(256) __nv_bfloat16 g_RWT_BF[(size_t)K_DIM * E_DIM];   // rec_w^T (K,E)
__device__ __align__(256) __nv_bfloat16 g_XP_BF[(size_t)B_DIM * K_DIM];    // xp / yp bf16
__device__ __align__(256) __nv_bfloat16 g_LAT_BF[(size_t)B_DIM * E_DIM];   // lat bf16

// ---------------------------------------------------------------------------
// Small PTX helpers
// ---------------------------------------------------------------------------
__device__ __forceinline__ uint32_t smem_u32(const void* p) {
    return (uint32_t)__cvta_generic_to_shared(p);
}
__device__ __forceinline__ void cp16(void* s, const void* g) {
    uint32_t sa = smem_u32(s);
    asm volatile("cp.async.cg.shared.global [%0], [%1], 16;" :: "r"(sa), "l"(g));
}
__device__ __forceinline__ void ldsm_x4(uint32_t addr, uint32_t& r0, uint32_t& r1,
                                        uint32_t& r2, uint32_t& r3) {
    asm volatile("ldmatrix.sync.aligned.m8n8.x4.shared.b16 {%0,%1,%2,%3}, [%4];"
                 : "=r"(r0), "=r"(r1), "=r"(r2), "=r"(r3) : "r"(addr));
}
__device__ __forceinline__ void mma16816(float* c, const uint32_t* a, uint32_t b0, uint32_t b1) {
    asm volatile(
        "mma.sync.aligned.m16n8k16.row.col.f32.bf16.bf16.f32 "
        "{%0,%1,%2,%3},{%4,%5,%6,%7},{%8,%9},{%0,%1,%2,%3};"
        : "+f"(c[0]), "+f"(c[1]), "+f"(c[2]), "+f"(c[3])
        : "r"(a[0]), "r"(a[1]), "r"(a[2]), "r"(a[3]), "r"(b0), "r"(b1));
}

// Byte offset of 16B chunk (r, cc) inside a 128x32 bf16 tile (row stride 64B).
// Swizzle cc ^ ((r>>1)&3): all 8 rows of an ldmatrix phase hit distinct 16B granules.
__device__ __forceinline__ int tile_off(int r, int cc) {
    return r * 64 + ((cc ^ ((r >> 1) & 3)) * 16);
}

// epilogue store helpers
__device__ __forceinline__ void store2(float* C, size_t off, float x, float y) {
    *(float2*)(C + off) = make_float2(x, y);
}
__device__ __forceinline__ void store2(__nv_bfloat16* C, size_t off, float x, float y) {
    *(__nv_bfloat162*)(C + off) = __floats2bfloat162_rn(x, y);
}

// ---------------------------------------------------------------------------
// bf16 NT GEMM: C[M,N] = A[M,Kd] (row-major bf16) * B[N,Kd]^T (row-major bf16)
// CTA tile 128x128x32, 8 warps (2x4), warp tile 64x32, 3-stage cp.async.
// M,N multiples of 128; Kd multiple of 32.
// ---------------------------------------------------------------------------
#define NSTAGE 3
#define STAGE_BYTES 16384   // A tile 8KB + B tile 8KB

template <typename OutT>
__global__ __launch_bounds__(256, 2)
void gemm_bf16(OutT* __restrict__ C, const __nv_bfloat16* __restrict__ A,
               const __nv_bfloat16* __restrict__ Bm, int M, int N, int Kd) {
    __shared__ __align__(16) unsigned char sm[NSTAGE * STAGE_BYTES];

    const int t = threadIdx.x;
    const int lane = t & 31;
    const int wid = t >> 5;
    const int wm = wid >> 2;   // 0..1
    const int wn = wid & 3;    // 0..3
    const int m0 = blockIdx.y * 128;
    const int n0 = blockIdx.x * 128;

    // cp.async addressing: thread t loads row r = t>>1, chunks (t&1)*2, (t&1)*2+1
    const int r = t >> 1;
    const int half = t & 1;
    const __nv_bfloat16* Agp = A + (size_t)(m0 + r) * Kd + half * 16;
    const __nv_bfloat16* Bgp = Bm + (size_t)(n0 + r) * Kd + half * 16;
    const int so0 = tile_off(r, half * 2);
    const int so1 = tile_off(r, half * 2 + 1);

    float acc[4][4][4];
#pragma unroll
    for (int i = 0; i < 4; i++)
#pragma unroll
        for (int j = 0; j < 4; j++)
#pragma unroll
            for (int q = 0; q < 4; q++) acc[i][j][q] = 0.0f;

    const int nk = Kd / 32;

    // Prologue: fill NSTAGE-1 stages
#pragma unroll
    for (int s = 0; s < NSTAGE - 1; s++) {
        unsigned char* base = sm + s * STAGE_BYTES;
        const __nv_bfloat16* ag = Agp + s * 32;
        const __nv_bfloat16* bg = Bgp + s * 32;
        cp16(base + so0, ag);
        cp16(base + so1, ag + 8);
        cp16(base + 8192 + so0, bg);
        cp16(base + 8192 + so1, bg + 8);
        asm volatile("cp.async.commit_group;" ::: "memory");
    }

    for (int kt = 0; kt < nk; kt++) {
        asm volatile("cp.async.wait_group 1;" ::: "memory");
        __syncthreads();

        unsigned char* As = sm + (kt % NSTAGE) * STAGE_BYTES;
        unsigned char* Bs = As + 8192;

#pragma unroll
        for (int ks = 0; ks < 2; ks++) {
            uint32_t a[4][4], b[2][4];
#pragma unroll
            for (int mt = 0; mt < 4; mt++) {
                int rr = wm * 64 + mt * 16 + (lane & 15);
                int ch = ks * 2 + (lane >> 4);
                ldsm_x4(smem_u32(As + tile_off(rr, ch)),
                        a[mt][0], a[mt][1], a[mt][2], a[mt][3]);
            }
#pragma unroll
            for (int g = 0; g < 2; g++) {
                int nr = wn * 32 + g * 16 + ((lane >> 4) & 1) * 8 + (lane & 7);
                int ch = ks * 2 + ((lane >> 3) & 1);
                ldsm_x4(smem_u32(Bs + tile_off(nr, ch)),
                        b[g][0], b[g][1], b[g][2], b[g][3]);
            }
#pragma unroll
            for (int mt = 0; mt < 4; mt++)
#pragma unroll
                for (int nt = 0; nt < 4; nt++) {
                    uint32_t b0 = b[nt >> 1][(nt & 1) * 2];
                    uint32_t b1 = b[nt >> 1][(nt & 1) * 2 + 1];
                    mma16816(acc[mt][nt], a[mt], b0, b1);
                }
        }

        const int nxt = kt + NSTAGE - 1;
        if (nxt < nk) {
            unsigned char* base = sm + (nxt % NSTAGE) * STAGE_BYTES;
            const __nv_bfloat16* ag = Agp + nxt * 32;
            const __nv_bfloat16* bg = Bgp + nxt * 32;
            cp16(base + so0, ag);
            cp16(base + so1, ag + 8);
            cp16(base + 8192 + so0, bg);
            cp16(base + 8192 + so1, bg + 8);
        }
        asm volatile("cp.async.commit_group;" ::: "memory");
    }

    // Epilogue
#pragma unroll
    for (int mt = 0; mt < 4; mt++) {
        int row = m0 + wm * 64 + mt * 16 + (lane >> 2);
#pragma unroll
        for (int nt = 0; nt < 4; nt++) {
            int col = n0 + wn * 32 + nt * 8 + (lane & 3) * 2;
            store2(C, (size_t)row * N + col, acc[mt][nt][0], acc[mt][nt][1]);
            store2(C, (size_t)(row + 8) * N + col, acc[mt][nt][2], acc[mt][nt][3]);
        }
    }
}

// ---------------------------------------------------------------------------
// Conversion / transpose kernels
// ---------------------------------------------------------------------------
__global__ void conv_bf16_kernel(const float* __restrict__ in, __nv_bfloat16* __restrict__ out,
                                 int n4) {
    int i = blockIdx.x * blockDim.x + threadIdx.x;
    if (i < n4) {
        float4 v = ((const float4*)in)[i];
        ((__nv_bfloat162*)out)[2 * i]     = __floats2bfloat162_rn(v.x, v.y);
        ((__nv_bfloat162*)out)[2 * i + 1] = __floats2bfloat162_rn(v.z, v.w);
    }
}

// out (C x R) bf16 = transpose of in (R x C) fp32. R, C multiples of 32.
__global__ void transpose_bf16_kernel(const float* __restrict__ in, __nv_bfloat16* __restrict__ out,
                                      int R, int C) {
    __shared__ float tile[32][33];
    int x = blockIdx.x * 32 + threadIdx.x;
    int y0 = blockIdx.y * 32;
#pragma unroll
    for (int j = 0; j < 32; j += 8)
        tile[threadIdx.y + j][threadIdx.x] = in[(size_t)(y0 + threadIdx.y + j) * C + x];
    __syncthreads();
    int xo = blockIdx.y * 32 + threadIdx.x;
    int yo0 = blockIdx.x * 32;
#pragma unroll
    for (int j = 0; j < 32; j += 8)
        out[(size_t)(yo0 + threadIdx.y + j) * R + xo] =
            __float2bfloat16(tile[threadIdx.x][threadIdx.y + j]);
}

// ---------------------------------------------------------------------------
// Row softmax over K=2048 cols: logit = a*S[row,k] - BETA*c2[k]; out bf16.
// (per-row x2 term dropped: constant along softmax axis => shift-invariant)
// ---------------------------------------------------------------------------
__global__ void softmax_kernel(const float* __restrict__ S, __nv_bfloat16* __restrict__ O,
                               const float* __restrict__ c2, float a) {
    const int row = blockIdx.x;
    const int t = threadIdx.x;
    const int lane = t & 31, wid = t >> 5;
    const float* s = S + (size_t)row * K_DIM;
    __nv_bfloat16* o = O + (size_t)row * K_DIM;
    __shared__ float wmax[8], wsum[8];

    float vals[8];
    float mx = -INFINITY;
#pragma unroll
    for (int i = 0; i < 8; i++) {
        int k = t + i * 256;
        float v = fmaf(a, s[k], -BETA_F * c2[k]);
        vals[i] = v;
        mx = fmaxf(mx, v);
    }
#pragma unroll
    for (int off = 16; off; off >>= 1) mx = fmaxf(mx, __shfl_xor_sync(0xffffffffu, mx, off));
    if (lane == 0) wmax[wid] = mx;
    __syncthreads();
    float m = wmax[0];
#pragma unroll
    for (int w = 1; w < 8; w++) m = fmaxf(m, wmax[w]);

    float sum = 0.0f;
#pragma unroll
    for (int i = 0; i < 8; i++) {
        vals[i] = expf(vals[i] - m);
        sum += vals[i];
    }
#pragma unroll
    for (int off = 16; off; off >>= 1) sum += __shfl_xor_sync(0xffffffffu, sum, off);
    if (lane == 0) wsum[wid] = sum;
    __syncthreads();
    float tot = wsum[0];
#pragma unroll
    for (int w = 1; w < 8; w++) tot += wsum[w];
    float inv = 1.0f / tot;
#pragma unroll
    for (int i = 0; i < 8; i++) o[t + i * 256] = __float2bfloat16(vals[i] * inv);
}

// ---------------------------------------------------------------------------
// Norm precomputes + loss
// ---------------------------------------------------------------------------
__device__ __forceinline__ float block_sum256(float v, float* red) {
    int t = threadIdx.x;
    red[t] = v;
    __syncthreads();
#pragma unroll
    for (int s = 128; s > 0; s >>= 1) {
        if (t < s) red[t] += red[t + s];
        __syncthreads();
    }
    float r = red[0];
    __syncthreads();
    return r;
}

__global__ void rowmeansq_kernel(const float* __restrict__ W, float* __restrict__ out, int cols) {
    __shared__ float red[256];
    const int row = blockIdx.x, t = threadIdx.x;
    const float* w = W + (size_t)row * cols;
    float s = 0.0f;
    for (int c = t; c < cols; c += 256) { float v = w[c]; s += v * v; }
    s = block_sum256(s, red);
    if (t == 0) out[row] = s / (float)cols;
}

__global__ void colmeansq_kernel(const float* __restrict__ W, float* __restrict__ out,
                                 int rows, int cols) {
    int k = blockIdx.x * blockDim.x + threadIdx.x;
    if (k < cols) {
        float s = 0.0f;
        for (int e = 0; e < rows; e++) { float v = W[(size_t)e * cols + k]; s += v * v; }
        out[k] = s / (float)rows;
    }
}

__global__ void loss_kernel(const float* __restrict__ recon, const float* __restrict__ img,
                            float* __restrict__ out, int cols) {
    __shared__ float red[256];
    const int row = blockIdx.x, t = threadIdx.x;
    const float* rr = recon + (size_t)row * cols;
    const float* x = img + (size_t)row * cols;
    float s = 0.0f;
    for (int c = t; c < cols; c += 256) { float d = rr[c] - x[c]; s += d * d; }
    s = block_sum256(s, red);
    if (t == 0) out[row] = s / (float)cols;
}

// ---------------------------------------------------------------------------
// Launch
// ---------------------------------------------------------------------------
extern "C" void kernel_launch(void* const* d_in, const int* in_sizes, int n_in,
                              void* d_out, int out_size) {
    const float* images    = (const float*)d_in[0];   // (B, D)
    const float* project_w = (const float*)d_in[1];   // (K, D)
    const float* rec_w     = (const float*)d_in[2];   // (E, K)
    float* loss_out        = (float*)d_out;           // (B,)

    float *S, *REC, *C2, *C2B;
    __nv_bfloat16 *IMG, *PW, *PWT, *RW, *RWT, *XP, *LAT;
    cudaGetSymbolAddress((void**)&S,   g_S);
    cudaGetSymbolAddress((void**)&REC, g_REC);
    cudaGetSymbolAddress((void**)&C2,  g_C2);
    cudaGetSymbolAddress((void**)&C2B, g_C2B);
    cudaGetSymbolAddress((void**)&IMG, g_IMG_BF);
    cudaGetSymbolAddress((void**)&PW,  g_PW_BF);
    cudaGetSymbolAddress((void**)&PWT, g_PWT_BF);
    cudaGetSymbolAddress((void**)&RW,  g_RW_BF);
    cudaGetSymbolAddress((void**)&RWT, g_RWT_BF);
    cudaGetSymbolAddress((void**)&XP,  g_XP_BF);
    cudaGetSymbolAddress((void**)&LAT, g_LAT_BF);

    // bf16 conversions + transposes
    {
        int n4 = (B_DIM * D_DIM) / 4;
        conv_bf16_kernel<<<(n4 + 255) / 256, 256>>>(images, IMG, n4);
        n4 = (K_DIM * D_DIM) / 4;
        conv_bf16_kernel<<<(n4 + 255) / 256, 256>>>(project_w, PW, n4);
        n4 = (E_DIM * K_DIM) / 4;
        conv_bf16_kernel<<<(n4 + 255) / 256, 256>>>(rec_w, RW, n4);
        transpose_bf16_kernel<<<dim3(D_DIM / 32, K_DIM / 32), dim3(32, 8)>>>(project_w, PWT, K_DIM, D_DIM);
        transpose_bf16_kernel<<<dim3(K_DIM / 32, E_DIM / 32), dim3(32, 8)>>>(rec_w, RWT, E_DIM, K_DIM);
    }

    // Column-norm precomputes
    rowmeansq_kernel<<<K_DIM, 256>>>(project_w, C2, D_DIM);
    colmeansq_kernel<<<K_DIM / 256, 256>>>(rec_w, C2B, E_DIM, K_DIM);

    // G1 (NT): S = images @ project_w^T   (B x K), Kd = D
    gemm_bf16<float><<<dim3(K_DIM / 128, B_DIM / 128), 256>>>(S, IMG, PW, B_DIM, K_DIM, D_DIM);

    // softmax1 -> xp (bf16)
    softmax_kernel<<<B_DIM, 256>>>(S, XP, C2, BETA_F * 2.0f / (float)D_DIM);

    // G2 (NT): lat = xp @ rec_w^T   (B x E), Kd = K, bf16 out
    gemm_bf16<__nv_bfloat16><<<dim3(E_DIM / 128, B_DIM / 128), 256>>>(LAT, XP, RW, B_DIM, E_DIM, K_DIM);

    // G3 (NT via rec_w^T): S = lat @ rec_w   (B x K), Kd = E
    gemm_bf16<float><<<dim3(K_DIM / 128, B_DIM / 128), 256>>>(S, LAT, RWT, B_DIM, K_DIM, E_DIM);

    // softmax2 -> yp (bf16)
    softmax_kernel<<<B_DIM, 256>>>(S, XP, C2B, BETA_F * 2.0f / (float)E_DIM);

    // G4 (NT via project_w^T): recon = yp @ project_w   (B x D), Kd = K
    gemm_bf16<float><<<dim3(D_DIM / 128, B_DIM / 128), 256>>>(REC, XP, PWT, B_DIM, D_DIM, K_DIM);

    // loss
    loss_kernel<<<B_DIM, 256>>>(REC, images, loss_out, D_DIM);
}

// round 7
// speedup vs baseline: 9.2398x; 1.0704x over previous
#include <cuda_runtime.h>
#include <cuda_bf16.h>
#include <math.h>
#include <stdint.h>

// Problem constants
#define B_DIM 8192
#define D_DIM 1024
#define K_DIM 2048
#define E_DIM 512
#define BETA_F 0.001f

// ---------------------------------------------------------------------------
// Scratch (device globals: allocation-free per harness rules)
// ---------------------------------------------------------------------------
__device__ __align__(256) __nv_bfloat16 g_S_BF[(size_t)B_DIM * K_DIM];    // logits cross (bf16)
__device__ __align__(256) float g_REC[(size_t)B_DIM * D_DIM];             // recon fp32
__device__ __align__(256) float g_C2[K_DIM];
__device__ __align__(256) float g_C2B[K_DIM];

__device__ __align__(256) __nv_bfloat16 g_IMG_BF[(size_t)B_DIM * D_DIM];  // images bf16
__device__ __align__(256) __nv_bfloat16 g_PW_BF[(size_t)K_DIM * D_DIM];   // project_w (K,D)
__device__ __align__(256) __nv_bfloat16 g_PWT_BF[(size_t)D_DIM * K_DIM];  // project_w^T (D,K)
__device__ __align__(256) __nv_bfloat16 g_RW_BF[(size_t)E_DIM * K_DIM];   // rec_w (E,K)
__device__ __align__(256) __nv_bfloat16 g_RWT_BF[(size_t)K_DIM * E_DIM];  // rec_w^T (K,E)
__device__ __align__(256) __nv_bfloat16 g_XP_BF[(size_t)B_DIM * K_DIM];   // xp / yp bf16
__device__ __align__(256) __nv_bfloat16 g_LAT_BF[(size_t)B_DIM * E_DIM];  // lat bf16

// ---------------------------------------------------------------------------
// PTX helpers
// ---------------------------------------------------------------------------
__device__ __forceinline__ uint32_t smem_u32(const void* p) {
    return (uint32_t)__cvta_generic_to_shared(p);
}
__device__ __forceinline__ void cp16(void* s, const void* g) {
    uint32_t sa = smem_u32(s);
    asm volatile("cp.async.cg.shared.global [%0], [%1], 16;" :: "r"(sa), "l"(g));
}
__device__ __forceinline__ void ldsm_x4(uint32_t addr, uint32_t& r0, uint32_t& r1,
                                        uint32_t& r2, uint32_t& r3) {
    asm volatile("ldmatrix.sync.aligned.m8n8.x4.shared.b16 {%0,%1,%2,%3}, [%4];"
                 : "=r"(r0), "=r"(r1), "=r"(r2), "=r"(r3) : "r"(addr));
}
__device__ __forceinline__ void mma16816(float* c, const uint32_t* a, uint32_t b0, uint32_t b1) {
    asm volatile(
        "mma.sync.aligned.m16n8k16.row.col.f32.bf16.bf16.f32 "
        "{%0,%1,%2,%3},{%4,%5,%6,%7},{%8,%9},{%0,%1,%2,%3};"
        : "+f"(c[0]), "+f"(c[1]), "+f"(c[2]), "+f"(c[3])
        : "r"(a[0]), "r"(a[1]), "r"(a[2]), "r"(a[3]), "r"(b0), "r"(b1));
}

// Byte offset of 16B chunk (r, cc) in a tile with 64B rows (32 bf16 cols).
// Swizzle cc ^ ((r>>1)&3): conflict-free ldmatrix phases (validated in R5).
__device__ __forceinline__ int tile_off(int r, int cc) {
    return r * 64 + ((cc ^ ((r >> 1) & 3)) * 16);
}

// epilogue store helpers
__device__ __forceinline__ void store2(float* C, size_t off, float x, float y) {
    *(float2*)(C + off) = make_float2(x, y);
}
__device__ __forceinline__ void store2(__nv_bfloat16* C, size_t off, float x, float y) {
    *(__nv_bfloat162*)(C + off) = __floats2bfloat162_rn(x, y);
}

// ---------------------------------------------------------------------------
// bf16 NT GEMM: C[M,N] = A[M,Kd] (row-major bf16) * B[N,Kd]^T (row-major bf16)
// CTA tile 128x256x32, 8 warps (2x4), warp tile 64x64, 4-stage cp.async.
// M % 128 == 0, N % 256 == 0, Kd % 32 == 0.
// ---------------------------------------------------------------------------
#define NSTAGE 4
#define A_BYTES 8192                      // 128 rows x 64B
#define B_BYTES 16384                     // 256 rows x 64B
#define STAGE_BYTES (A_BYTES + B_BYTES)   // 24 KB
#define GEMM_SMEM (NSTAGE * STAGE_BYTES)  // 96 KB

template <typename OutT>
__global__ __launch_bounds__(256, 1)
void gemm_bf16(OutT* __restrict__ C, const __nv_bfloat16* __restrict__ A,
               const __nv_bfloat16* __restrict__ Bm, int M, int N, int Kd) {
    extern __shared__ __align__(16) unsigned char sm[];

    const int t = threadIdx.x;
    const int lane = t & 31;
    const int wid = t >> 5;
    const int wm = wid >> 2;   // 0..1 (64-row half)
    const int wn = wid & 3;    // 0..3 (64-col quarter)
    const int m0 = blockIdx.y * 128;
    const int n0 = blockIdx.x * 256;
    const int nk = Kd / 32;

    // cp.async mapping: 1536 x 16B chunks per stage; thread t does g = t + i*256.
    // g < 512 -> A (rows 0..127, 4 chunks/row); g >= 512 -> B (rows 0..255).
    auto load_tile = [&](int stage, int kt) {
        unsigned char* base = sm + stage * STAGE_BYTES;
#pragma unroll
        for (int i = 0; i < 2; i++) {        // A chunks
            int g = t + i * 256;
            int r = g >> 2, cc = g & 3;
            cp16(base + tile_off(r, cc),
                 A + (size_t)(m0 + r) * Kd + kt * 32 + cc * 8);
        }
#pragma unroll
        for (int i = 2; i < 6; i++) {        // B chunks
            int g = t + i * 256;
            int r = (g >> 2) - 128, cc = g & 3;
            cp16(base + A_BYTES + tile_off(r, cc),
                 Bm + (size_t)(n0 + r) * Kd + kt * 32 + cc * 8);
        }
    };

    float acc[4][8][4];
#pragma unroll
    for (int i = 0; i < 4; i++)
#pragma unroll
        for (int j = 0; j < 8; j++)
#pragma unroll
            for (int q = 0; q < 4; q++) acc[i][j][q] = 0.0f;

    // Prologue: fill NSTAGE-1 = 3 stages
#pragma unroll
    for (int s = 0; s < NSTAGE - 1; s++) {
        load_tile(s, s);
        asm volatile("cp.async.commit_group;" ::: "memory");
    }

    for (int kt = 0; kt < nk; kt++) {
        asm volatile("cp.async.wait_group 2;" ::: "memory");
        __syncthreads();

        unsigned char* As = sm + (kt & (NSTAGE - 1)) * STAGE_BYTES;
        unsigned char* Bs = As + A_BYTES;

#pragma unroll
        for (int ks = 0; ks < 2; ks++) {
            uint32_t a[4][4], b[4][4];
#pragma unroll
            for (int mt = 0; mt < 4; mt++) {
                int rr = wm * 64 + mt * 16 + (lane & 15);
                int ch = ks * 2 + (lane >> 4);
                ldsm_x4(smem_u32(As + tile_off(rr, ch)),
                        a[mt][0], a[mt][1], a[mt][2], a[mt][3]);
            }
#pragma unroll
            for (int g = 0; g < 4; g++) {
                int nr = wn * 64 + g * 16 + ((lane >> 4) & 1) * 8 + (lane & 7);
                int ch = ks * 2 + ((lane >> 3) & 1);
                ldsm_x4(smem_u32(Bs + tile_off(nr, ch)),
                        b[g][0], b[g][1], b[g][2], b[g][3]);
            }
#pragma unroll
            for (int mt = 0; mt < 4; mt++)
#pragma unroll
                for (int nt = 0; nt < 8; nt++) {
                    uint32_t b0 = b[nt >> 1][(nt & 1) * 2];
                    uint32_t b1 = b[nt >> 1][(nt & 1) * 2 + 1];
                    mma16816(acc[mt][nt], a[mt], b0, b1);
                }
        }

        const int nxt = kt + NSTAGE - 1;
        if (nxt < nk) {
            load_tile(nxt & (NSTAGE - 1), nxt);
        }
        asm volatile("cp.async.commit_group;" ::: "memory");
    }

    // Epilogue
#pragma unroll
    for (int mt = 0; mt < 4; mt++) {
        int row = m0 + wm * 64 + mt * 16 + (lane >> 2);
#pragma unroll
        for (int nt = 0; nt < 8; nt++) {
            int col = n0 + wn * 64 + nt * 8 + (lane & 3) * 2;
            store2(C, (size_t)row * N + col, acc[mt][nt][0], acc[mt][nt][1]);
            store2(C, (size_t)(row + 8) * N + col, acc[mt][nt][2], acc[mt][nt][3]);
        }
    }
}

// ---------------------------------------------------------------------------
// Conversion / transpose kernels
// ---------------------------------------------------------------------------
__global__ void conv_bf16_kernel(const float* __restrict__ in, __nv_bfloat16* __restrict__ out,
                                 int n4) {
    int i = blockIdx.x * blockDim.x + threadIdx.x;
    if (i < n4) {
        float4 v = ((const float4*)in)[i];
        ((__nv_bfloat162*)out)[2 * i]     = __floats2bfloat162_rn(v.x, v.y);
        ((__nv_bfloat162*)out)[2 * i + 1] = __floats2bfloat162_rn(v.z, v.w);
    }
}

// out (C x R) bf16 = transpose of in (R x C) fp32. R, C multiples of 32.
__global__ void transpose_bf16_kernel(const float* __restrict__ in,
                                      __nv_bfloat16* __restrict__ out, int R, int C) {
    __shared__ float tile[32][33];
    int x = blockIdx.x * 32 + threadIdx.x;
    int y0 = blockIdx.y * 32;
#pragma unroll
    for (int j = 0; j < 32; j += 8)
        tile[threadIdx.y + j][threadIdx.x] = in[(size_t)(y0 + threadIdx.y + j) * C + x];
    __syncthreads();
    int xo = blockIdx.y * 32 + threadIdx.x;
    int yo0 = blockIdx.x * 32;
#pragma unroll
    for (int j = 0; j < 32; j += 8)
        out[(size_t)(yo0 + threadIdx.y + j) * R + xo] =
            __float2bfloat16(tile[threadIdx.x][threadIdx.y + j]);
}

// ---------------------------------------------------------------------------
// Row softmax over K=2048 cols (bf16 in / bf16 out), one uint4 per thread.
// logit = a*S[row,k] - BETA*c2[k]   (shift-invariant x2 term dropped)
// ---------------------------------------------------------------------------
__global__ void softmax_kernel(const __nv_bfloat16* __restrict__ S,
                               __nv_bfloat16* __restrict__ O,
                               const float* __restrict__ c2, float a) {
    const int row = blockIdx.x;
    const int t = threadIdx.x;
    const int lane = t & 31, wid = t >> 5;
    __shared__ float wred[8];

    uint4 v = ((const uint4*)(S + (size_t)row * K_DIM))[t];
    float f[8];
    {
        __nv_bfloat162 h;
        h = *(__nv_bfloat162*)&v.x; f[0] = __low2float(h); f[1] = __high2float(h);
        h = *(__nv_bfloat162*)&v.y; f[2] = __low2float(h); f[3] = __high2float(h);
        h = *(__nv_bfloat162*)&v.z; f[4] = __low2float(h); f[5] = __high2float(h);
        h = *(__nv_bfloat162*)&v.w; f[6] = __low2float(h); f[7] = __high2float(h);
    }
    const float4 c0 = *(const float4*)(c2 + t * 8);
    const float4 c1 = *(const float4*)(c2 + t * 8 + 4);
    f[0] = fmaf(a, f[0], -BETA_F * c0.x); f[1] = fmaf(a, f[1], -BETA_F * c0.y);
    f[2] = fmaf(a, f[2], -BETA_F * c0.z); f[3] = fmaf(a, f[3], -BETA_F * c0.w);
    f[4] = fmaf(a, f[4], -BETA_F * c1.x); f[5] = fmaf(a, f[5], -BETA_F * c1.y);
    f[6] = fmaf(a, f[6], -BETA_F * c1.z); f[7] = fmaf(a, f[7], -BETA_F * c1.w);

    float mx = f[0];
#pragma unroll
    for (int i = 1; i < 8; i++) mx = fmaxf(mx, f[i]);
#pragma unroll
    for (int off = 16; off; off >>= 1) mx = fmaxf(mx, __shfl_xor_sync(0xffffffffu, mx, off));
    if (lane == 0) wred[wid] = mx;
    __syncthreads();
    float m = wred[0];
#pragma unroll
    for (int w = 1; w < 8; w++) m = fmaxf(m, wred[w]);
    __syncthreads();

    float sum = 0.0f;
#pragma unroll
    for (int i = 0; i < 8; i++) {
        f[i] = expf(f[i] - m);
        sum += f[i];
    }
#pragma unroll
    for (int off = 16; off; off >>= 1) sum += __shfl_xor_sync(0xffffffffu, sum, off);
    if (lane == 0) wred[wid] = sum;
    __syncthreads();
    float tot = wred[0];
#pragma unroll
    for (int w = 1; w < 8; w++) tot += wred[w];
    const float inv = 1.0f / tot;

    uint32_t w0, w1, w2, w3;
    __nv_bfloat162 h;
    h = __floats2bfloat162_rn(f[0] * inv, f[1] * inv); w0 = *(uint32_t*)&h;
    h = __floats2bfloat162_rn(f[2] * inv, f[3] * inv); w1 = *(uint32_t*)&h;
    h = __floats2bfloat162_rn(f[4] * inv, f[5] * inv); w2 = *(uint32_t*)&h;
    h = __floats2bfloat162_rn(f[6] * inv, f[7] * inv); w3 = *(uint32_t*)&h;
    ((uint4*)(O + (size_t)row * K_DIM))[t] = make_uint4(w0, w1, w2, w3);
}

// ---------------------------------------------------------------------------
// Norm precomputes + loss
// ---------------------------------------------------------------------------
__device__ __forceinline__ float block_sum256(float v, float* red) {
    int t = threadIdx.x;
    red[t] = v;
    __syncthreads();
#pragma unroll
    for (int s = 128; s > 0; s >>= 1) {
        if (t < s) red[t] += red[t + s];
        __syncthreads();
    }
    float r = red[0];
    __syncthreads();
    return r;
}

__global__ void rowmeansq_kernel(const float* __restrict__ W, float* __restrict__ out, int cols) {
    __shared__ float red[256];
    const int row = blockIdx.x, t = threadIdx.x;
    const float* w = W + (size_t)row * cols;
    float s = 0.0f;
    for (int c = t; c < cols; c += 256) { float v = w[c]; s += v * v; }
    s = block_sum256(s, red);
    if (t == 0) out[row] = s / (float)cols;
}

__global__ void colmeansq_kernel(const float* __restrict__ W, float* __restrict__ out,
                                 int rows, int cols) {
    int k = blockIdx.x * blockDim.x + threadIdx.x;
    if (k < cols) {
        float s = 0.0f;
        for (int e = 0; e < rows; e++) { float v = W[(size_t)e * cols + k]; s += v * v; }
        out[k] = s / (float)rows;
    }
}

__global__ void loss_kernel(const float* __restrict__ recon, const float* __restrict__ img,
                            float* __restrict__ out, int cols) {
    __shared__ float red[256];
    const int row = blockIdx.x, t = threadIdx.x;
    const float* rr = recon + (size_t)row * cols;
    const float* x = img + (size_t)row * cols;
    float s = 0.0f;
    for (int c = t; c < cols; c += 256) { float d = rr[c] - x[c]; s += d * d; }
    s = block_sum256(s, red);
    if (t == 0) out[row] = s / (float)cols;
}

// ---------------------------------------------------------------------------
// Launch
// ---------------------------------------------------------------------------
extern "C" void kernel_launch(void* const* d_in, const int* in_sizes, int n_in,
                              void* d_out, int out_size) {
    const float* images    = (const float*)d_in[0];   // (B, D)
    const float* project_w = (const float*)d_in[1];   // (K, D)
    const float* rec_w     = (const float*)d_in[2];   // (E, K)
    float* loss_out        = (float*)d_out;           // (B,)

    float *REC, *C2, *C2B;
    __nv_bfloat16 *S, *IMG, *PW, *PWT, *RW, *RWT, *XP, *LAT;
    cudaGetSymbolAddress((void**)&S,   g_S_BF);
    cudaGetSymbolAddress((void**)&REC, g_REC);
    cudaGetSymbolAddress((void**)&C2,  g_C2);
    cudaGetSymbolAddress((void**)&C2B, g_C2B);
    cudaGetSymbolAddress((void**)&IMG, g_IMG_BF);
    cudaGetSymbolAddress((void**)&PW,  g_PW_BF);
    cudaGetSymbolAddress((void**)&PWT, g_PWT_BF);
    cudaGetSymbolAddress((void**)&RW,  g_RW_BF);
    cudaGetSymbolAddress((void**)&RWT, g_RWT_BF);
    cudaGetSymbolAddress((void**)&XP,  g_XP_BF);
    cudaGetSymbolAddress((void**)&LAT, g_LAT_BF);

    cudaFuncSetAttribute(gemm_bf16<__nv_bfloat16>,
                         cudaFuncAttributeMaxDynamicSharedMemorySize, GEMM_SMEM);
    cudaFuncSetAttribute(gemm_bf16<float>,
                         cudaFuncAttributeMaxDynamicSharedMemorySize, GEMM_SMEM);

    // bf16 conversions + transposes
    {
        int n4 = (B_DIM * D_DIM) / 4;
        conv_bf16_kernel<<<(n4 + 255) / 256, 256>>>(images, IMG, n4);
        n4 = (K_DIM * D_DIM) / 4;
        conv_bf16_kernel<<<(n4 + 255) / 256, 256>>>(project_w, PW, n4);
        n4 = (E_DIM * K_DIM) / 4;
        conv_bf16_kernel<<<(n4 + 255) / 256, 256>>>(rec_w, RW, n4);
        transpose_bf16_kernel<<<dim3(D_DIM / 32, K_DIM / 32), dim3(32, 8)>>>(project_w, PWT, K_DIM, D_DIM);
        transpose_bf16_kernel<<<dim3(K_DIM / 32, E_DIM / 32), dim3(32, 8)>>>(rec_w, RWT, E_DIM, K_DIM);
    }

    // Column-norm precomputes
    rowmeansq_kernel<<<K_DIM, 256>>>(project_w, C2, D_DIM);
    colmeansq_kernel<<<K_DIM / 256, 256>>>(rec_w, C2B, E_DIM, K_DIM);

    // G1 (NT): S = images @ project_w^T  (B x K), Kd = D  -> bf16
    gemm_bf16<__nv_bfloat16><<<dim3(K_DIM / 256, B_DIM / 128), 256, GEMM_SMEM>>>(
        S, IMG, PW, B_DIM, K_DIM, D_DIM);

    // softmax1 -> xp (bf16)
    softmax_kernel<<<B_DIM, 256>>>(S, XP, C2, BETA_F * 2.0f / (float)D_DIM);

    // G2 (NT): lat = xp @ rec_w^T  (B x E), Kd = K  -> bf16
    gemm_bf16<__nv_bfloat16><<<dim3(E_DIM / 256, B_DIM / 128), 256, GEMM_SMEM>>>(
        LAT, XP, RW, B_DIM, E_DIM, K_DIM);

    // G3 (NT via rec_w^T): S = lat @ rec_w  (B x K), Kd = E  -> bf16
    gemm_bf16<__nv_bfloat16><<<dim3(K_DIM / 256, B_DIM / 128), 256, GEMM_SMEM>>>(
        S, LAT, RWT, B_DIM, K_DIM, E_DIM);

    // softmax2 -> yp (bf16)
    softmax_kernel<<<B_DIM, 256>>>(S, XP, C2B, BETA_F * 2.0f / (float)E_DIM);

    // G4 (NT via project_w^T): recon = yp @ project_w  (B x D), Kd = K  -> fp32
    gemm_bf16<float><<<dim3(D_DIM / 256, B_DIM / 128), 256, GEMM_SMEM>>>(
        REC, XP, PWT, B_DIM, D_DIM, K_DIM);

    // loss
    loss_kernel<<<B_DIM, 256>>>(REC, images, loss_out, D_DIM);
}